// round 17
// baseline (speedup 1.0000x reference)
#include <cuda_runtime.h>
#include <cuda_bf16.h>
#include <cuda_fp16.h>
#include <stdint.h>

#define NN 50000
#define EE 800000
#define DD 256
#define LL 3
#define GG 512
#define ND (LL * DD)   // 768
#define MTILES 782     // ceil(NN/64)

// ---------------------------------------------------------------------------
// Device scratch: three persistent fp16 layer buffers (also pooled from)
// ---------------------------------------------------------------------------
__device__ __half g_x16[(size_t)NN * DD];
__device__ __half g_ha[(size_t)NN * DD];
__device__ __half g_hb[(size_t)NN * DD];
__device__ __half g_hc[(size_t)NN * DD];
__device__ int    g_deg[NN];
__device__ int    g_off[NN + 1];
__device__ int    g_cur[NN];
__device__ int    g_csr[EE];
__device__ int    g_counts[GG];
__device__ int    g_tilectr[4];          // per-layer dynamic tile counters
__device__ __half g_wt[6 * 256 * 256];   // fp16-rounded W, transposed [N][K]

// ---------------------------------------------------------------------------
// PTX helpers (sm_80-era only)
// ---------------------------------------------------------------------------
__device__ __forceinline__ uint32_t smem_u32(const void* p) {
    uint32_t a;
    asm("{ .reg .u64 t; cvta.to.shared.u64 t, %1; cvt.u32.u64 %0, t; }" : "=r"(a) : "l"(p));
    return a;
}
__device__ __forceinline__ void ldsm4(uint32_t* r, uint32_t addr) {
    asm volatile("ldmatrix.sync.aligned.m8n8.x4.shared.b16 {%0,%1,%2,%3}, [%4];"
        : "=r"(r[0]), "=r"(r[1]), "=r"(r[2]), "=r"(r[3]) : "r"(addr));
}
__device__ __forceinline__ void mma_f16(float* d, const uint32_t* a, const uint32_t* b) {
    asm volatile("mma.sync.aligned.m16n8k16.row.col.f32.f16.f16.f32 "
        "{%0,%1,%2,%3}, {%4,%5,%6,%7}, {%8,%9}, {%0,%1,%2,%3};"
        : "+f"(d[0]), "+f"(d[1]), "+f"(d[2]), "+f"(d[3])
        : "r"(a[0]), "r"(a[1]), "r"(a[2]), "r"(a[3]), "r"(b[0]), "r"(b[1]));
}
#define CP_ASYNC16(dst, src) \
    asm volatile("cp.async.cg.shared.global [%0], [%1], 16;" :: "r"(dst), "l"(src) : "memory")
#define CP_COMMIT() asm volatile("cp.async.commit_group;" ::: "memory")
#define CP_WAIT1()  asm volatile("cp.async.wait_group 1;" ::: "memory")
#define CP_WAIT0()  asm volatile("cp.async.wait_group 0;" ::: "memory")

// ---------------------------------------------------------------------------
// Setup kernels
// ---------------------------------------------------------------------------
__global__ void init_zero_kernel(int* __restrict__ deg, int* __restrict__ counts,
                                 int* __restrict__ tilectr, float* __restrict__ gev) {
    int i = blockIdx.x * blockDim.x + threadIdx.x;
    if (i < NN) deg[i] = 0;
    if (i < GG) counts[i] = 0;
    if (i < 4) tilectr[i] = 0;
    if (i < GG * ND) gev[i] = 0.0f;
}

__global__ void deg_count_kernel(const int* __restrict__ dst, const int* __restrict__ batch,
                                 int* __restrict__ deg, int* __restrict__ counts) {
    int i = blockIdx.x * blockDim.x + threadIdx.x;
    if (i < EE) atomicAdd(&deg[dst[i]], 1);
    if (i < NN) atomicAdd(&counts[batch[i]], 1);
}

__global__ void scan_kernel(const int* __restrict__ deg, int* __restrict__ off,
                            int* __restrict__ cur) {
    __shared__ int warp_sums[32];
    __shared__ int carry_s;
    const int tid = threadIdx.x;
    const int lane = tid & 31;
    const int wid = tid >> 5;
    if (tid == 0) carry_s = 0;
    __syncthreads();

    for (int base = 0; base < NN; base += 1024) {
        int i = base + tid;
        int v = (i < NN) ? deg[i] : 0;
        int incl = v;
#pragma unroll
        for (int o = 1; o < 32; o <<= 1) {
            int t = __shfl_up_sync(0xFFFFFFFFu, incl, o);
            if (lane >= o) incl += t;
        }
        if (lane == 31) warp_sums[wid] = incl;
        __syncthreads();
        if (wid == 0) {
            int ws = warp_sums[lane];
#pragma unroll
            for (int o = 1; o < 32; o <<= 1) {
                int t = __shfl_up_sync(0xFFFFFFFFu, ws, o);
                if (lane >= o) ws += t;
            }
            warp_sums[lane] = ws;
        }
        __syncthreads();
        int excl = incl - v + (wid > 0 ? warp_sums[wid - 1] : 0) + carry_s;
        if (i < NN) { off[i] = excl; cur[i] = excl; }
        __syncthreads();
        if (tid == 1023) carry_s = excl + v;
        __syncthreads();
    }
    if (tid == 0) off[NN] = carry_s;
}

__global__ void fill_kernel(const int* __restrict__ src, const int* __restrict__ dst,
                            int* __restrict__ cur, int* __restrict__ csr) {
    int e = blockIdx.x * blockDim.x + threadIdx.x;
    if (e >= EE) return;
    int d = dst[e];
    int p = atomicAdd(&cur[d], 1);
    csr[p] = src[e];
}

// transpose + fp16 round of the 6 weight matrices; output [N][K] row-major
__global__ void wprep_kernel(const float* __restrict__ Ws1, const float* __restrict__ Ws2,
                             __half* __restrict__ wh) {
    int i = blockIdx.x * blockDim.x + threadIdx.x;
    if (i >= 6 * 65536) return;
    int mat = i >> 16;
    int rem = i & 65535;
    int k = rem >> 8, n = rem & 255;
    const float* W = (mat < 3) ? (Ws1 + (size_t)mat * 65536) : (Ws2 + (size_t)(mat - 3) * 65536);
    float x = W[k * 256 + n];
    wh[((size_t)mat << 16) + (size_t)n * 256 + k] = __float2half_rn(x);
}

// x -> fp16 (one time)
__global__ void xcvt_kernel(const float* __restrict__ x, __half* __restrict__ x16) {
    int i = blockIdx.x * blockDim.x + threadIdx.x;
    if (i >= NN * DD / 4) return;
    float4 v = __ldg((const float4*)x + i);
    __half2 a = __floats2half2_rn(v.x, v.y);
    __half2 b = __floats2half2_rn(v.z, v.w);
    uint2 o;
    o.x = *(uint32_t*)&a;
    o.y = *(uint32_t*)&b;
    *((uint2*)x16 + i) = o;
}

// ---------------------------------------------------------------------------
// Fused layer kernel: persistent CTAs, dynamic tiles.
// Per tile: gather -> GEMM1 -> (t in smem) -> GEMM2 -> h + node_embed.
// M-tile 64, 256 threads (8 warps), 2 CTAs/SM.
// smem: A/t tile fp16 (64 x 528B = 33.8KB) + triple-buffered W (3 x 8KB) = 58.4KB
// ---------------------------------------------------------------------------
#define BM 64
#define AT_STR 528
#define OFF_B 33792                // 64*528
#define B_BUFSZ 8192               // 256 rows * 32B
#define FUSED_SMEM 58368           // 33792 + 3*8192
#define NCHUNK 16                  // K/16
#define GRID_PERSIST 296           // 2 * 148 SMs

// B smem swizzle: row n, 16B-segment s (0/1): off = n*32 + ((s*16) ^ ((n&4)<<2))
__device__ __forceinline__ void issue_b_chunk(uint32_t sb,
        const __half* __restrict__ Wh, int kb, int buf, int tid) {
#pragma unroll
    for (int j = 0; j < 2; j++) {
        int i = tid + j * 256;            // 0..511
        int n = i >> 1;                   // 0..255
        int seg = i & 1;                  // 16B segment of 32B row
        const __half* src = Wh + (size_t)n * DD + kb + seg * 8;
        uint32_t dst = sb + OFF_B + (uint32_t)buf * B_BUFSZ
                     + (uint32_t)n * 32 + (((uint32_t)seg * 16) ^ (((uint32_t)n & 4) << 2));
        CP_ASYNC16(dst, src);
    }
    CP_COMMIT();
}

__device__ __forceinline__ ushort2 pack_h2(float a, float b) {
    ushort2 r;
    r.x = __half_as_ushort(__float2half_rn(a));
    r.y = __half_as_ushort(__float2half_rn(b));
    return r;
}

__device__ __forceinline__ void acc_u4(float* acc, uint4 v) {
    float2 f0 = __half22float2(*(__half2*)&v.x);
    float2 f1 = __half22float2(*(__half2*)&v.y);
    float2 f2 = __half22float2(*(__half2*)&v.z);
    float2 f3 = __half22float2(*(__half2*)&v.w);
    acc[0] += f0.x; acc[1] += f0.y; acc[2] += f1.x; acc[3] += f1.y;
    acc[4] += f2.x; acc[5] += f2.y; acc[6] += f3.x; acc[7] += f3.y;
}

// Triple-buffered GEMM phase: chunk0 must already be issued into buf 0.
// One __syncthreads per chunk; final sync before epilogue.
template <bool TO_SMEM>
__device__ __forceinline__ void gemm_phase(char* smem, uint32_t sb,
        const __half* __restrict__ Wh,
        const float* __restrict__ bias, int bm,
        __half* __restrict__ hout, float* __restrict__ ne) {
    const int tid = threadIdx.x;
    const int lane = tid & 31;
    const int w = tid >> 5;
    const int wm = (w & 1) * 32;          // 2 M-groups of 32
    const int wn = (w >> 1) * 64;         // 4 N-groups of 64
    const int frow = (lane & 7) + ((lane & 8) ? 8 : 0);
    const int fkc  = ((lane & 16) ? 8 : 0);
    const int brow = (lane & 7) + ((lane & 16) ? 8 : 0);
    const int bkc  = ((lane & 8) ? 8 : 0);

    float acc[2][8][4];
#pragma unroll
    for (int mi = 0; mi < 2; mi++)
#pragma unroll
        for (int nj = 0; nj < 8; nj++)
#pragma unroll
            for (int q = 0; q < 4; q++) acc[mi][nj][q] = 0.0f;

#pragma unroll 1
    for (int c = 0; c < NCHUNK; c++) {
        if (c < NCHUNK - 1) {
            issue_b_chunk(sb, Wh, (c + 1) * 16, (c + 1) % 3, tid);
            CP_WAIT1();                     // chunk c complete (newest = c+1)
        } else {
            CP_WAIT0();
        }
        __syncthreads();                    // single barrier per chunk

        const uint32_t bh_base = sb + OFF_B + (uint32_t)(c % 3) * B_BUFSZ;
        const int kA = c * 16;

        uint32_t ah[2][4];
#pragma unroll
        for (int mi = 0; mi < 2; mi++) {
            uint32_t o = (uint32_t)(wm + mi * 16 + frow) * AT_STR + (uint32_t)(kA + fkc) * 2;
            ldsm4(ah[mi], sb + o);
        }
#pragma unroll
        for (int p = 0; p < 4; p++) {
            const uint32_t nrow = (uint32_t)(wn + p * 16 + brow);
            const uint32_t o = nrow * 32 + (((uint32_t)bkc * 2) ^ ((nrow & 4) << 2));
            uint32_t th[4];
            ldsm4(th, bh_base + o);
            uint32_t b0h[2] = {th[0], th[1]}, b1h[2] = {th[2], th[3]};
#pragma unroll
            for (int mi = 0; mi < 2; mi++) {
                mma_f16(acc[mi][2 * p],     ah[mi], b0h);
                mma_f16(acc[mi][2 * p + 1], ah[mi], b1h);
            }
        }
    }
    __syncthreads();   // all reads of A/B done before epilogue overwrites / next phase

    // epilogue
    const int g2 = lane >> 2;
    const int tg2 = (lane & 3) * 2;
#pragma unroll
    for (int mi = 0; mi < 2; mi++) {
        const int r0l = wm + mi * 16 + g2;
        const int r1l = r0l + 8;
#pragma unroll
        for (int nj = 0; nj < 8; nj++) {
            const int col = wn + nj * 8 + tg2;
            float b0 = __ldg(&bias[col]);
            float b1 = __ldg(&bias[col + 1]);
            float v00 = fmaxf(acc[mi][nj][0] + b0, 0.0f);
            float v01 = fmaxf(acc[mi][nj][1] + b1, 0.0f);
            float v10 = fmaxf(acc[mi][nj][2] + b0, 0.0f);
            float v11 = fmaxf(acc[mi][nj][3] + b1, 0.0f);
            if (TO_SMEM) {
                uint32_t o0 = (uint32_t)r0l * AT_STR + (uint32_t)col * 2;
                uint32_t o1 = (uint32_t)r1l * AT_STR + (uint32_t)col * 2;
                *(ushort2*)(smem + o0) = pack_h2(v00, v01);
                *(ushort2*)(smem + o1) = pack_h2(v10, v11);
            } else {
                const int r0 = bm + r0l, r1 = bm + r1l;
                if (r0 < NN) {
                    ushort2 hv = pack_h2(v00, v01);
                    *(ushort2*)(hout + (size_t)r0 * DD + col) = hv;
                    *(float2*)(ne + (size_t)r0 * ND + col) = make_float2(v00, v01);
                }
                if (r1 < NN) {
                    ushort2 hv = pack_h2(v10, v11);
                    *(ushort2*)(hout + (size_t)r1 * DD + col) = hv;
                    *(float2*)(ne + (size_t)r1 * ND + col) = make_float2(v10, v11);
                }
            }
        }
    }
}

__global__ __launch_bounds__(256, 2)
void fused_layer_kernel(const __half* __restrict__ hin,
                        const int* __restrict__ off, const int* __restrict__ csr,
                        const __half* __restrict__ W1h, const float* __restrict__ b1,
                        const __half* __restrict__ W2h, const float* __restrict__ b2,
                        __half* __restrict__ hout, float* __restrict__ ne,
                        int* __restrict__ tile_ctr) {
    extern __shared__ char smem[];
    __shared__ int s_tile;
    const uint32_t sb = smem_u32(smem);
    const int tid = threadIdx.x;
    const int lane = tid & 31;
    const int w = tid >> 5;

    const uint4* __restrict__ h16 = (const uint4*)hin;   // 32 uint4 per fp16 row

    while (true) {
        if (tid == 0) s_tile = atomicAdd(tile_ctr, 1);
        __syncthreads();                       // broadcast tile; also guards A reuse
        const int tile = s_tile;
        if (tile >= MTILES) break;
        const int bm = tile * BM;

        // start W1 chunk0 (buf 0) early; overlaps gather
        issue_b_chunk(sb, W1h, 0, 0, tid);

        // ---- gather: warp-per-row, coalesced CSR index fetch + shfl ----
#pragma unroll 1
        for (int rr = 0; rr < 8; rr++) {
            const int rl = w * 8 + rr;
            const int gr = bm + rl;
            float acc[8];
#pragma unroll
            for (int q = 0; q < 8; q++) acc[q] = 0.0f;
            if (gr < NN) {
                acc_u4(acc, __ldg(&h16[(size_t)gr * 32 + lane]));
                int j = __ldg(&off[gr]);
                const int je = __ldg(&off[gr + 1]);
                while (j < je) {
                    const int cnt = min(32, je - j);
                    int myidx = (lane < cnt) ? __ldg(&csr[j + lane]) : 0;
                    int e = 0;
                    for (; e + 4 <= cnt; e += 4) {
                        int s0 = __shfl_sync(0xFFFFFFFFu, myidx, e);
                        int s1 = __shfl_sync(0xFFFFFFFFu, myidx, e + 1);
                        int s2 = __shfl_sync(0xFFFFFFFFu, myidx, e + 2);
                        int s3 = __shfl_sync(0xFFFFFFFFu, myidx, e + 3);
                        uint4 v0 = __ldg(&h16[(size_t)s0 * 32 + lane]);
                        uint4 v1 = __ldg(&h16[(size_t)s1 * 32 + lane]);
                        uint4 v2 = __ldg(&h16[(size_t)s2 * 32 + lane]);
                        uint4 v3 = __ldg(&h16[(size_t)s3 * 32 + lane]);
                        acc_u4(acc, v0);
                        acc_u4(acc, v1);
                        acc_u4(acc, v2);
                        acc_u4(acc, v3);
                    }
                    for (; e < cnt; e++) {
                        int s0 = __shfl_sync(0xFFFFFFFFu, myidx, e);
                        acc_u4(acc, __ldg(&h16[(size_t)s0 * 32 + lane]));
                    }
                    j += cnt;
                }
            }
            // fp16 round; lane owns cols [8*lane, 8*lane+8)
            char* base = smem + (uint32_t)rl * AT_STR + (uint32_t)lane * 16;
            ushort2 h0 = pack_h2(acc[0], acc[1]);
            ushort2 h1 = pack_h2(acc[2], acc[3]);
            ushort2 h2 = pack_h2(acc[4], acc[5]);
            ushort2 h3 = pack_h2(acc[6], acc[7]);
            uint4 hv;
            hv.x = (uint32_t)h0.x | ((uint32_t)h0.y << 16);
            hv.y = (uint32_t)h1.x | ((uint32_t)h1.y << 16);
            hv.z = (uint32_t)h2.x | ((uint32_t)h2.y << 16);
            hv.w = (uint32_t)h3.x | ((uint32_t)h3.y << 16);
            *(uint4*)(base) = hv;
        }
        __syncthreads();

        // phase 1: t = relu(agg @ W1 + b1) -> smem (overwrites A tile)
        gemm_phase<true>(smem, sb, W1h, b1, bm, nullptr, nullptr);
        __syncthreads();

        // phase 2: h = relu(t @ W2 + b2) -> gmem (fp16 hout + fp32 node_embed)
        issue_b_chunk(sb, W2h, 0, 0, tid);
        gemm_phase<false>(smem, sb, W2h, b2, bm, hout, ne);
    }
}

// ---------------------------------------------------------------------------
// Pooling with run compression (batch sorted); reads fp16 layer buffers
// ---------------------------------------------------------------------------
__global__ __launch_bounds__(256)
void pool_kernel(const int* __restrict__ batch,
                 const __half* __restrict__ h1, const __half* __restrict__ h2,
                 const __half* __restrict__ h3, float* __restrict__ gev) {
    const int l = blockIdx.y;
    const __half* __restrict__ hb = (l == 0) ? h1 : (l == 1) ? h2 : h3;
    const int c = threadIdx.x;
    const int n0 = blockIdx.x * 128;
    int n1 = n0 + 128; if (n1 > NN) n1 = NN;

    int g = __ldg(&batch[n0]);
    float acc = 0.0f;
    for (int n = n0; n < n1; n++) {
        int gn = __ldg(&batch[n]);
        if (gn != g) {
            atomicAdd(&gev[(size_t)g * ND + l * DD + c], acc);
            acc = 0.0f;
            g = gn;
        }
        acc += __half2float(__ldg(&hb[(size_t)n * DD + c]));
    }
    atomicAdd(&gev[(size_t)g * ND + l * DD + c], acc);
}

__global__ void divide_kernel(float* __restrict__ gev, const int* __restrict__ counts) {
    int i = blockIdx.x * blockDim.x + threadIdx.x;
    if (i >= GG * ND) return;
    int g = i / ND;
    int cnt = counts[g];
    gev[i] *= 1.0f / (float)(cnt > 0 ? cnt : 1);
}

// ---------------------------------------------------------------------------
// Launch
// ---------------------------------------------------------------------------
extern "C" void kernel_launch(void* const* d_in, const int* in_sizes, int n_in,
                              void* d_out, int out_size) {
    const float* x          = (const float*)d_in[0];
    const int*   edge_index = (const int*)d_in[1];
    const int*   batch      = (const int*)d_in[2];
    const float* Ws1        = (const float*)d_in[3];
    const float* bs1        = (const float*)d_in[4];
    const float* Ws2        = (const float*)d_in[5];
    const float* bs2        = (const float*)d_in[6];

    float* out = (float*)d_out;
    float* graph_embed = out;
    float* node_embed  = out + (size_t)GG * ND;

    __half* x16; cudaGetSymbolAddress((void**)&x16, g_x16);
    __half* ha;  cudaGetSymbolAddress((void**)&ha,  g_ha);
    __half* hb;  cudaGetSymbolAddress((void**)&hb,  g_hb);
    __half* hc;  cudaGetSymbolAddress((void**)&hc,  g_hc);
    int* deg;    cudaGetSymbolAddress((void**)&deg, g_deg);
    int* off;    cudaGetSymbolAddress((void**)&off, g_off);
    int* cur;    cudaGetSymbolAddress((void**)&cur, g_cur);
    int* csr;    cudaGetSymbolAddress((void**)&csr, g_csr);
    int* counts; cudaGetSymbolAddress((void**)&counts, g_counts);
    int* tilectr; cudaGetSymbolAddress((void**)&tilectr, g_tilectr);
    __half* wt;  cudaGetSymbolAddress((void**)&wt,  g_wt);

    cudaFuncSetAttribute(fused_layer_kernel, cudaFuncAttributeMaxDynamicSharedMemorySize, FUSED_SMEM);

    const int* esrc = edge_index;
    const int* edst = edge_index + EE;

    // ---- setup launches ----
    init_zero_kernel<<<(GG * ND + 255) / 256, 256>>>(deg, counts, tilectr, graph_embed);
    deg_count_kernel<<<(EE + 255) / 256, 256>>>(edst, batch, deg, counts);
    scan_kernel<<<1, 1024>>>(deg, off, cur);
    fill_kernel<<<(EE + 255) / 256, 256>>>(esrc, edst, cur, csr);
    wprep_kernel<<<(6 * 65536 + 255) / 256, 256>>>(Ws1, Ws2, wt);
    xcvt_kernel<<<(NN * DD / 4 + 255) / 256, 256>>>(x, x16);

    // layer chain: x16 -> ha -> hb -> hc (all persist for pooling)
    const __half* hin = x16;
    __half* houts[LL] = {ha, hb, hc};
    for (int l = 0; l < LL; l++) {
        fused_layer_kernel<<<GRID_PERSIST, 256, FUSED_SMEM>>>(
            hin, off, csr,
            wt + (size_t)l * 65536, bs1 + l * DD,
            wt + (size_t)(3 + l) * 65536, bs2 + l * DD,
            houts[l], node_embed + (size_t)l * DD,
            tilectr + l);
        hin = houts[l];
    }

    dim3 pgrid((NN + 127) / 128, LL);
    pool_kernel<<<pgrid, 256>>>(batch, ha, hb, hc, graph_embed);
    divide_kernel<<<(GG * ND + 255) / 256, 256>>>(graph_embed, counts);
}